// round 14
// baseline (speedup 1.0000x reference)
#include <cuda_runtime.h>
#include <cuda_fp16.h>
#include <math_constants.h>
#include <cstdint>

// Problem constants
#define Bv 4
#define Sv 2048
#define Ev 1024
#define Hv 16
#define HDv 64
#define NKB (Sv / 64)
#define ATT_SCALE 0.125f
#define LOG2E 1.4426950408889634f

// ========================= PTX helpers =====================================
__device__ __forceinline__ uint32_t smem_u32(const void* p) {
    uint32_t a;
    asm("{ .reg .u64 t; cvta.to.shared.u64 t, %1; cvt.u32.u64 %0, t; }"
        : "=r"(a) : "l"(p));
    return a;
}
#define CP_ASYNC16(sa, ga) \
    asm volatile("cp.async.cg.shared.global [%0], [%1], 16;" :: "r"(sa), "l"(ga))
#define CP_COMMIT()  asm volatile("cp.async.commit_group;" ::: "memory")
#define CP_WAIT(n)   asm volatile("cp.async.wait_group %0;" :: "n"(n) : "memory")

#define MBAR_INIT(addr, cnt) \
    asm volatile("mbarrier.init.shared.b64 [%0], %1;" :: "r"(addr), "r"((uint32_t)(cnt)) : "memory")
#define MBAR_ARRIVE(addr) \
    asm volatile("mbarrier.arrive.shared.b64 _, [%0];" :: "r"(addr) : "memory")
#define CPA_ARRIVE(addr) \
    asm volatile("cp.async.mbarrier.arrive.noinc.shared.b64 [%0];" :: "r"(addr) : "memory")
#define MBAR_WAIT(addr, ph) \
    asm volatile("{\n\t.reg .pred P;\n" \
                 "WL_%=:\n\t" \
                 "mbarrier.try_wait.parity.acquire.cta.shared::cta.b64 P, [%0], %1;\n\t" \
                 "@!P bra WL_%=;\n\t}" \
                 :: "r"(addr), "r"((uint32_t)(ph)) : "memory")

__device__ __forceinline__ void ldsm4(uint32_t addr, uint32_t r[4]) {
    asm volatile("ldmatrix.sync.aligned.m8n8.x4.shared.b16 {%0,%1,%2,%3}, [%4];"
                 : "=r"(r[0]), "=r"(r[1]), "=r"(r[2]), "=r"(r[3]) : "r"(addr));
}
__device__ __forceinline__ void ldsm4t(uint32_t addr, uint32_t r[4]) {
    asm volatile("ldmatrix.sync.aligned.m8n8.x4.trans.shared.b16 {%0,%1,%2,%3}, [%4];"
                 : "=r"(r[0]), "=r"(r[1]), "=r"(r[2]), "=r"(r[3]) : "r"(addr));
}
__device__ __forceinline__ void mma_fp(float c[4], const uint32_t a[4],
                                       const uint32_t b[2]) {
    asm volatile(
        "mma.sync.aligned.m16n8k16.row.col.f32.f16.f16.f32 "
        "{%0,%1,%2,%3}, {%4,%5,%6,%7}, {%8,%9}, {%0,%1,%2,%3};"
        : "+f"(c[0]), "+f"(c[1]), "+f"(c[2]), "+f"(c[3])
        : "r"(a[0]), "r"(a[1]), "r"(a[2]), "r"(a[3]), "r"(b[0]), "r"(b[1]));
}
__device__ __forceinline__ uint32_t f2_to_h2u(float lo, float hi) {
    uint32_t r;
    asm("cvt.rn.f16x2.f32 %0, %1, %2;" : "=r"(r) : "f"(hi), "f"(lo));
    return r;
}
__device__ __forceinline__ float ex2f(float x) {
    float r; asm("ex2.approx.f32 %0, %1;" : "=f"(r) : "f"(x)); return r;
}
__device__ __forceinline__ uint32_t h2ex2(uint32_t a) {
    uint32_t r; asm("ex2.approx.f16x2 %0, %1;" : "=r"(r) : "r"(a)); return r;
}

// ========================= static device scratch ===========================
__device__ __half g_Qh[(size_t)Bv * Sv * Ev];
__device__ __half g_Kh[(size_t)Bv * Sv * Ev];
__device__ __half g_Vh[(size_t)Bv * Sv * Ev];
__device__ __half g_xf[(size_t)Bv * Sv * Ev];
__device__ __half g_of[(size_t)Bv * Sv * Ev];
__device__ __half g_wf[4][(size_t)Ev * Ev];

// ========================= fused fp32 -> fp16 convert ======================
__global__ void cvt_all_kernel(const float* __restrict__ x,
                               const float* __restrict__ w0,
                               const float* __restrict__ w1,
                               const float* __restrict__ w2,
                               const float* __restrict__ w3,
                               __half* __restrict__ xf, __half* __restrict__ wf)
{
    const int bid = blockIdx.x;
    const float* src;
    __half* dst;
    int i;
    if (bid < 8192) {
        src = x; dst = xf;
        i = bid * 256 + threadIdx.x;
    } else {
        const int wb = bid - 8192;
        const int wi = wb >> 10;
        const float* ws[4] = {w0, w1, w2, w3};
        src = ws[wi];
        dst = wf + (size_t)wi * Ev * Ev;
        i = (wb & 1023) * 256 + threadIdx.x;
    }
    float4 v = reinterpret_cast<const float4*>(src)[i];
    uint32_t* dp = reinterpret_cast<uint32_t*>(dst) + 2 * i;
    dp[0] = f2_to_h2u(v.x, v.y);
    dp[1] = f2_to_h2u(v.z, v.w);
}

// ========================= shared GEMM config (R12 best) ===================
// 128x128 CTA tile, 4 warps of 64x64, 128 threads, BK=32, 4-stage pipeline.
#define BK 32
#define ROWB 80
#define TILE_BYTES (128 * ROWB)
#define NCHW (Ev / BK)
#define STAGE_S (2 * TILE_BYTES)
#define NGSTG 4
#define GEMM_SMEM (NGSTG * STAGE_S)   // 81920
#define GTHREADS 128

__device__ __forceinline__ void load_stage_s(
    uint32_t sbase, int stage, int kc,
    const __half* A, const __half* B, int m0, int n0, int tid)
{
    const uint32_t st = sbase + stage * STAGE_S;
    const __half* srcs[2] = {A, B};
    const int row0[2] = {m0, n0};
#pragma unroll
    for (int t = 0; t < 2; ++t) {
#pragma unroll
        for (int p = 0; p < 4; ++p) {
            const int i = p * GTHREADS + tid;
            const int r = i >> 2;
            const int c = i & 3;
            const __half* g =
                srcs[t] + (size_t)(row0[t] + r) * Ev + kc * BK + c * 8;
            CP_ASYNC16(st + t * TILE_BYTES + r * ROWB + c * 16, g);
        }
    }
}

#define GEMM_MAINLOOP(A_, B_)                                              \
    load_stage_s(sb, 0, 0, A_, B_, m0, n0, tid); CP_COMMIT();              \
    load_stage_s(sb, 1, 1, A_, B_, m0, n0, tid); CP_COMMIT();              \
    load_stage_s(sb, 2, 2, A_, B_, m0, n0, tid); CP_COMMIT();              \
    CP_WAIT(2);                                                            \
    __syncthreads();                                                       \
    for (int c = 0; c < NCHW; ++c) {                                       \
        const int s = c & 3;                                               \
        if (c + 3 < NCHW) {                                                \
            load_stage_s(sb, (c + 3) & 3, c + 3, A_, B_, m0, n0, tid);     \
            CP_COMMIT();                                                   \
        } else { CP_COMMIT(); }                                            \
        const uint32_t stA = sb + s * STAGE_S;                             \
        const uint32_t stB = stA + TILE_BYTES;                             \
        _Pragma("unroll")                                                  \
        for (int ks = 0; ks < 2; ++ks) {                                   \
            const uint32_t kofs = ks * 32;                                 \
            uint32_t a[4][4], b[4][4];                                     \
            _Pragma("unroll")                                              \
            for (int p = 0; p < 4; ++p)                                    \
                ldsm4(stA + (uint32_t)(arow + p * 16) * ROWB + kofs + acol16, a[p]); \
            _Pragma("unroll")                                              \
            for (int p = 0; p < 4; ++p)                                    \
                ldsm4(stB + (uint32_t)(nrow + p * 16) * ROWB + kofs + bcol16, b[p]); \
            _Pragma("unroll")                                              \
            for (int mt = 0; mt < 4; ++mt)                                 \
                _Pragma("unroll")                                          \
                for (int nt = 0; nt < 8; ++nt)                             \
                    mma_fp(acc[mt][nt], a[mt], &b[nt >> 1][(nt & 1) * 2]); \
        }                                                                  \
        CP_WAIT(2);                                                        \
        __syncthreads();                                                   \
    }

// ========================= fused QKV GEMM (single-product fp16) ============
__global__ __launch_bounds__(GTHREADS, 2)
void gemm_qkv_kernel(const __half* __restrict__ A, const __half* __restrict__ W,
                     __half* __restrict__ Qo, __half* __restrict__ Ko,
                     __half* __restrict__ Vo)
{
    extern __shared__ __align__(128) char smem[];
    const uint32_t sb = smem_u32(smem);
    const int tid = threadIdx.x;
    const int wid = tid >> 5, lane = tid & 31;
    const int warp_m = wid & 1, warp_n = wid >> 1;
    const int m0 = blockIdx.y << 7;
    const int n0 = blockIdx.x << 7;
    const int z  = blockIdx.z;

    const __half* B = W + (size_t)z * Ev * Ev;
    __half* Out = (z == 0) ? Qo : ((z == 1) ? Ko : Vo);
    const float premul = (z == 0) ? (ATT_SCALE * LOG2E) : 1.0f;

    float acc[4][8][4];
#pragma unroll
    for (int mt = 0; mt < 4; ++mt)
#pragma unroll
        for (int nt = 0; nt < 8; ++nt)
#pragma unroll
            for (int q = 0; q < 4; ++q) acc[mt][nt][q] = 0.f;

    const int arow = warp_m * 64 + (lane & 15);
    const uint32_t acol16 = (uint32_t)((lane >> 4) << 4);
    const int nrow = warp_n * 64 + (((lane >> 4) & 1) << 3) + (lane & 7);
    const uint32_t bcol16 = (uint32_t)(((lane >> 3) & 1) << 4);

    GEMM_MAINLOOP(A, B)

    const int tr = lane >> 2;
    const int tc = (lane & 3) * 2;
    const int mb = m0 + warp_m * 64;
    const int nb = n0 + warp_n * 64;
#pragma unroll
    for (int mt = 0; mt < 4; ++mt) {
#pragma unroll
        for (int nt = 0; nt < 8; ++nt) {
            const int col = nb + nt * 8 + tc;
            const size_t r0 = (size_t)(mb + mt * 16 + tr) * Ev + col;
            const size_t r1 = (size_t)(mb + mt * 16 + tr + 8) * Ev + col;
            *reinterpret_cast<uint32_t*>(&Out[r0]) =
                f2_to_h2u(acc[mt][nt][0] * premul, acc[mt][nt][1] * premul);
            *reinterpret_cast<uint32_t*>(&Out[r1]) =
                f2_to_h2u(acc[mt][nt][2] * premul, acc[mt][nt][3] * premul);
        }
    }
}

// ========================= out-proj GEMM (single-product, fp32+bias) =======
__global__ __launch_bounds__(GTHREADS, 2)
void gemm_out_kernel(const __half* __restrict__ A, const __half* __restrict__ B,
                     const float* __restrict__ bias, float* __restrict__ C)
{
    extern __shared__ __align__(128) char smem[];
    const uint32_t sb = smem_u32(smem);
    const int tid = threadIdx.x;
    const int wid = tid >> 5, lane = tid & 31;
    const int warp_m = wid & 1, warp_n = wid >> 1;
    const int m0 = blockIdx.y << 7;
    const int n0 = blockIdx.x << 7;

    float acc[4][8][4];
#pragma unroll
    for (int mt = 0; mt < 4; ++mt)
#pragma unroll
        for (int nt = 0; nt < 8; ++nt)
#pragma unroll
            for (int q = 0; q < 4; ++q) acc[mt][nt][q] = 0.f;

    const int arow = warp_m * 64 + (lane & 15);
    const uint32_t acol16 = (uint32_t)((lane >> 4) << 4);
    const int nrow = warp_n * 64 + (((lane >> 4) & 1) << 3) + (lane & 7);
    const uint32_t bcol16 = (uint32_t)(((lane >> 3) & 1) << 4);

    GEMM_MAINLOOP(A, B)

    const int tr = lane >> 2;
    const int tc = (lane & 3) * 2;
    const int mb = m0 + warp_m * 64;
    const int nb = n0 + warp_n * 64;
#pragma unroll
    for (int mt = 0; mt < 4; ++mt) {
#pragma unroll
        for (int nt = 0; nt < 8; ++nt) {
            const int col = nb + nt * 8 + tc;
            const float b0 = bias[col], b1 = bias[col + 1];
            const size_t r0 = (size_t)(mb + mt * 16 + tr) * Ev + col;
            const size_t r1 = (size_t)(mb + mt * 16 + tr + 8) * Ev + col;
            float2 v0 = {acc[mt][nt][0] + b0, acc[mt][nt][1] + b1};
            float2 v1 = {acc[mt][nt][2] + b0, acc[mt][nt][3] + b1};
            *reinterpret_cast<float2*>(&C[r0]) = v0;
            *reinterpret_cast<float2*>(&C[r1]) = v1;
        }
    }
}

// ========================= tensor-core flash attention =====================
// 4 warps x 32 q-rows (K/V ldsm shared across 2 m-tiles -> crossbar relief).
// fp16, log2-domain scores, ex2.f16x2 P, ones-column row-sum MMA, skip-scale.
// Buggy l preserved. 3-stage mbarrier K/V pipeline. Output fp16.
#define ATHREADS 128
#define NSTG 3
#define KVSTG (2 * 64 * 144)
#define ATT_SMEM (64 + 128 * 144 + NSTG * KVSTG)
#define H2_ONES 0x3C003C00u

__global__ __launch_bounds__(ATHREADS, 2)
void attn_tc_kernel(const __half* __restrict__ Q, const __half* __restrict__ K,
                    const __half* __restrict__ V, __half* __restrict__ Of)
{
    extern __shared__ __align__(128) char smem[];
    const uint32_t sb = smem_u32(smem);
    const uint32_t sQ  = sb + 64;
    const uint32_t sKV = sQ + 128 * 144;

    const int tid = threadIdx.x;
    const int w = tid >> 5, lane = tid & 31;
    const int b  = blockIdx.x >> 4;
    const int h  = blockIdx.x & 15;
    const int q0 = blockIdx.y << 7;

    const __half* Qg = Q + ((size_t)b * Sv + q0) * Ev + h * HDv;
    const __half* Kg = K + (size_t)b * Sv * Ev + h * HDv;
    const __half* Vg = V + (size_t)b * Sv * Ev + h * HDv;

    if (tid == 0) {
#pragma unroll
        for (int s = 0; s < NSTG; ++s) {
            MBAR_INIT(sb + 8 * s, ATHREADS);
            MBAR_INIT(sb + 24 + 8 * s, ATHREADS);
        }
    }
    __syncthreads();

    for (int i = tid; i < 1024; i += ATHREADS) {
        const int r = i >> 3, c = i & 7;
        CP_ASYNC16(sQ + r * 144 + c * 16, Qg + (size_t)r * Ev + c * 8);
    }
    {
        const uint32_t st0 = sKV;
        for (int i = tid; i < 512; i += ATHREADS) {
            const int r = i >> 3, c = i & 7;
            CP_ASYNC16(st0 + r * 144 + c * 16, Kg + (size_t)r * Ev + c * 8);
            CP_ASYNC16(st0 + 64 * 144 + r * 144 + c * 16, Vg + (size_t)r * Ev + c * 8);
        }
        CPA_ARRIVE(sb + 0);
        const uint32_t st1 = sKV + KVSTG;
        const __half* Kp = Kg + (size_t)64 * Ev;
        const __half* Vp = Vg + (size_t)64 * Ev;
        for (int i = tid; i < 512; i += ATHREADS) {
            const int r = i >> 3, c = i & 7;
            CP_ASYNC16(st1 + r * 144 + c * 16, Kp + (size_t)r * Ev + c * 8);
            CP_ASYNC16(st1 + 64 * 144 + r * 144 + c * 16, Vp + (size_t)r * Ev + c * 8);
        }
        CPA_ARRIVE(sb + 8);
    }

    float acc[2][8][4];
#pragma unroll
    for (int mt = 0; mt < 2; ++mt)
#pragma unroll
        for (int j = 0; j < 8; ++j)
#pragma unroll
            for (int q = 0; q < 4; ++q) acc[mt][j][q] = 0.f;
    float rm[2][2], rl[2][2];
#pragma unroll
    for (int mt = 0; mt < 2; ++mt) {
        rm[mt][0] = -CUDART_INF_F; rm[mt][1] = -CUDART_INF_F;
        rl[mt][0] = 0.f; rl[mt][1] = 0.f;
    }

    uint32_t aQ[2][4][4];
    bool qLoaded = false;

    const uint32_t q_addr0 = sQ + (uint32_t)(32 * w + (lane & 15)) * 144
                                + ((lane >> 4) << 4);
    const int kq = lane & 7;
    const int kg16 = (lane >> 4) << 3;
    const int kg8  = ((lane >> 3) & 1) << 3;
    const uint32_t onesB[2] = {H2_ONES, H2_ONES};

    for (int kb = 0; kb < NKB; ++kb) {
        const int cur = kb % NSTG;
        MBAR_WAIT(sb + 8 * cur, (kb / NSTG) & 1);

        if (!qLoaded) {
#pragma unroll
            for (int mt = 0; mt < 2; ++mt)
#pragma unroll
                for (int s = 0; s < 4; ++s)
                    ldsm4(q_addr0 + (uint32_t)(mt * 16) * 144 + s * 32, aQ[mt][s]);
            qLoaded = true;
        }

        const uint32_t sKst = sKV + (uint32_t)cur * KVSTG;
        const uint32_t sVst = sKst + 64 * 144;

        // ---- scores: S[32][64] (2 m-tiles share each K fragment) ----
        float sc[2][8][4];
#pragma unroll
        for (int mt = 0; mt < 2; ++mt)
#pragma unroll
            for (int j = 0; j < 8; ++j)
#pragma unroll
                for (int q = 0; q < 4; ++q) sc[mt][j][q] = 0.f;

#pragma unroll
        for (int p = 0; p < 4; ++p) {
#pragma unroll
            for (int s = 0; s < 4; ++s) {
                uint32_t kf[4];
                ldsm4(sKst + (uint32_t)(16 * p + kg16 + kq) * 144
                           + (uint32_t)(16 * s + kg8) * 2, kf);
#pragma unroll
                for (int mt = 0; mt < 2; ++mt) {
                    mma_fp(sc[mt][2 * p],     aQ[mt][s], &kf[0]);
                    mma_fp(sc[mt][2 * p + 1], aQ[mt][s], &kf[2]);
                }
            }
        }

        // ---- produce stage for kb+2 ----
        if (kb + 2 < NKB) {
            const int kl = kb + 2;
            const int s2 = kl % NSTG;
            const int m = kl / NSTG;
            MBAR_WAIT(sb + 24 + 8 * s2, (m + 1) & 1);
            const uint32_t st = sKV + (uint32_t)s2 * KVSTG;
            const __half* Kp = Kg + (size_t)(kl * 64) * Ev;
            const __half* Vp = Vg + (size_t)(kl * 64) * Ev;
            for (int i = tid; i < 512; i += ATHREADS) {
                const int r = i >> 3, c = i & 7;
                CP_ASYNC16(st + r * 144 + c * 16, Kp + (size_t)r * Ev + c * 8);
                CP_ASYNC16(st + 64 * 144 + r * 144 + c * 16, Vp + (size_t)r * Ev + c * 8);
            }
            CPA_ARRIVE(sb + 8 * s2);
        }

        // ---- online softmax per m-tile (buggy l preserved) ----
        uint32_t ph01[2][8], ph23[2][8];
        float co[2][2];
#pragma unroll
        for (int mt = 0; mt < 2; ++mt) {
            float mx0 = -CUDART_INF_F, mx1 = -CUDART_INF_F;
#pragma unroll
            for (int j = 0; j < 8; ++j) {
                mx0 = fmaxf(mx0, fmaxf(sc[mt][j][0], sc[mt][j][1]));
                mx1 = fmaxf(mx1, fmaxf(sc[mt][j][2], sc[mt][j][3]));
            }
            mx0 = fmaxf(mx0, __shfl_xor_sync(0xffffffffu, mx0, 1));
            mx0 = fmaxf(mx0, __shfl_xor_sync(0xffffffffu, mx0, 2));
            mx1 = fmaxf(mx1, __shfl_xor_sync(0xffffffffu, mx1, 1));
            mx1 = fmaxf(mx1, __shfl_xor_sync(0xffffffffu, mx1, 2));

            const float mn0 = fmaxf(rm[mt][0], mx0);
            const float mn1 = fmaxf(rm[mt][1], mx1);
            co[mt][0] = 1.f; co[mt][1] = 1.f;
            if ((mn0 > rm[mt][0]) || (mn1 > rm[mt][1])) {
                co[mt][0] = ex2f(rm[mt][0] - mn0);
                co[mt][1] = ex2f(rm[mt][1] - mn1);
#pragma unroll
                for (int j = 0; j < 8; ++j) {
                    acc[mt][j][0] *= co[mt][0]; acc[mt][j][1] *= co[mt][0];
                    acc[mt][j][2] *= co[mt][1]; acc[mt][j][3] *= co[mt][1];
                }
            }
            rm[mt][0] = mn0; rm[mt][1] = mn1;

#pragma unroll
            for (int j = 0; j < 8; ++j) {
                ph01[mt][j] = h2ex2(f2_to_h2u(sc[mt][j][0] - mn0, sc[mt][j][1] - mn0));
                ph23[mt][j] = h2ex2(f2_to_h2u(sc[mt][j][2] - mn1, sc[mt][j][3] - mn1));
            }
        }

        // ---- PV + ones-column row-sum (V fragments shared across m-tiles) --
        float sl[2][4];
#pragma unroll
        for (int mt = 0; mt < 2; ++mt)
#pragma unroll
            for (int q = 0; q < 4; ++q) sl[mt][q] = 0.f;

#pragma unroll
        for (int s = 0; s < 4; ++s) {
            uint32_t aP[2][4];
#pragma unroll
            for (int mt = 0; mt < 2; ++mt) {
                aP[mt][0] = ph01[mt][2 * s];
                aP[mt][1] = ph23[mt][2 * s];
                aP[mt][2] = ph01[mt][2 * s + 1];
                aP[mt][3] = ph23[mt][2 * s + 1];
            }
#pragma unroll
            for (int dp = 0; dp < 4; ++dp) {
                uint32_t vf[4];
                ldsm4t(sVst + (uint32_t)(16 * s + kg8 + kq) * 144
                            + (uint32_t)(16 * dp + kg16) * 2, vf);
#pragma unroll
                for (int mt = 0; mt < 2; ++mt) {
                    mma_fp(acc[mt][2 * dp],     aP[mt], &vf[0]);
                    mma_fp(acc[mt][2 * dp + 1], aP[mt], &vf[2]);
                }
            }
#pragma unroll
            for (int mt = 0; mt < 2; ++mt)
                mma_fp(sl[mt], aP[mt], onesB);
        }
#pragma unroll
        for (int mt = 0; mt < 2; ++mt) {
            rl[mt][0] = fmaf(sl[mt][0], co[mt][0], sl[mt][0]);
            rl[mt][1] = fmaf(sl[mt][2], co[mt][1], sl[mt][2]);
        }

        MBAR_ARRIVE(sb + 24 + 8 * cur);
    }

    // ---- epilogue: O = acc / l, fp16 output ----
    const int colb = h * HDv + 2 * (lane & 3);
    __half* Ob = Of + (size_t)b * Sv * Ev;
#pragma unroll
    for (int mt = 0; mt < 2; ++mt) {
        const float inv0 = 1.f / rl[mt][0];
        const float inv1 = 1.f / rl[mt][1];
        const int row0 = q0 + 32 * w + 16 * mt + (lane >> 2);
#pragma unroll
        for (int j = 0; j < 8; ++j) {
            const int col = colb + 8 * j;
            const size_t i0 = (size_t)row0 * Ev + col;
            const size_t i1 = (size_t)(row0 + 8) * Ev + col;
            *reinterpret_cast<uint32_t*>(&Ob[i0]) =
                f2_to_h2u(acc[mt][j][0] * inv0, acc[mt][j][1] * inv0);
            *reinterpret_cast<uint32_t*>(&Ob[i1]) =
                f2_to_h2u(acc[mt][j][2] * inv1, acc[mt][j][3] * inv1);
        }
    }
}

// ========================= launch ==========================================
extern "C" void kernel_launch(void* const* d_in, const int* in_sizes, int n_in,
                              void* d_out, int out_size)
{
    const float* x  = (const float*)d_in[0];
    const float* qw = (const float*)d_in[1];
    const float* kw = (const float*)d_in[2];
    const float* vw = (const float*)d_in[3];
    const float* ow = (const float*)d_in[4];
    const float* ob = (const float*)d_in[5];
    float* out = (float*)d_out;

    __half *Qh, *Kh, *Vh, *xf, *of, *wf;
    cudaGetSymbolAddress((void**)&Qh, g_Qh);
    cudaGetSymbolAddress((void**)&Kh, g_Kh);
    cudaGetSymbolAddress((void**)&Vh, g_Vh);
    cudaGetSymbolAddress((void**)&xf, g_xf);
    cudaGetSymbolAddress((void**)&of, g_of);
    cudaGetSymbolAddress((void**)&wf, g_wf);

    const int M = Bv * Sv;

    cvt_all_kernel<<<8192 + 4096, 256>>>(x, qw, kw, vw, ow, xf, wf);

    cudaFuncSetAttribute(gemm_qkv_kernel,
                         cudaFuncAttributeMaxDynamicSharedMemorySize, GEMM_SMEM);
    cudaFuncSetAttribute(gemm_out_kernel,
                         cudaFuncAttributeMaxDynamicSharedMemorySize, GEMM_SMEM);
    cudaFuncSetAttribute(attn_tc_kernel,
                         cudaFuncAttributeMaxDynamicSharedMemorySize, ATT_SMEM);

    gemm_qkv_kernel<<<dim3(Ev / 128, M / 128, 3), GTHREADS, GEMM_SMEM>>>(
        xf, wf, Qh, Kh, Vh);

    attn_tc_kernel<<<dim3(Bv * Hv, Sv / 128), ATHREADS, ATT_SMEM>>>(Qh, Kh, Vh, of);

    gemm_out_kernel<<<dim3(Ev / 128, M / 128), GTHREADS, GEMM_SMEM>>>(
        of, wf + 3 * (size_t)Ev * Ev, ob, out);
}

// round 15
// speedup vs baseline: 1.0766x; 1.0766x over previous
#include <cuda_runtime.h>
#include <cuda_fp16.h>
#include <math_constants.h>
#include <cstdint>

// Problem constants
#define Bv 4
#define Sv 2048
#define Ev 1024
#define Hv 16
#define HDv 64
#define NKB (Sv / 64)
#define ATT_SCALE 0.125f
#define LOG2E 1.4426950408889634f

// ========================= PTX helpers =====================================
__device__ __forceinline__ uint32_t smem_u32(const void* p) {
    uint32_t a;
    asm("{ .reg .u64 t; cvta.to.shared.u64 t, %1; cvt.u32.u64 %0, t; }"
        : "=r"(a) : "l"(p));
    return a;
}
#define CP_ASYNC16(sa, ga) \
    asm volatile("cp.async.cg.shared.global [%0], [%1], 16;" :: "r"(sa), "l"(ga))
#define CP_COMMIT()  asm volatile("cp.async.commit_group;" ::: "memory")
#define CP_WAIT(n)   asm volatile("cp.async.wait_group %0;" :: "n"(n) : "memory")

#define MBAR_INIT(addr, cnt) \
    asm volatile("mbarrier.init.shared.b64 [%0], %1;" :: "r"(addr), "r"((uint32_t)(cnt)) : "memory")
#define MBAR_ARRIVE(addr) \
    asm volatile("mbarrier.arrive.shared.b64 _, [%0];" :: "r"(addr) : "memory")
#define CPA_ARRIVE(addr) \
    asm volatile("cp.async.mbarrier.arrive.noinc.shared.b64 [%0];" :: "r"(addr) : "memory")
#define MBAR_WAIT(addr, ph) \
    asm volatile("{\n\t.reg .pred P;\n" \
                 "WL_%=:\n\t" \
                 "mbarrier.try_wait.parity.acquire.cta.shared::cta.b64 P, [%0], %1;\n\t" \
                 "@!P bra WL_%=;\n\t}" \
                 :: "r"(addr), "r"((uint32_t)(ph)) : "memory")

__device__ __forceinline__ void ldsm4(uint32_t addr, uint32_t r[4]) {
    asm volatile("ldmatrix.sync.aligned.m8n8.x4.shared.b16 {%0,%1,%2,%3}, [%4];"
                 : "=r"(r[0]), "=r"(r[1]), "=r"(r[2]), "=r"(r[3]) : "r"(addr));
}
__device__ __forceinline__ void ldsm4t(uint32_t addr, uint32_t r[4]) {
    asm volatile("ldmatrix.sync.aligned.m8n8.x4.trans.shared.b16 {%0,%1,%2,%3}, [%4];"
                 : "=r"(r[0]), "=r"(r[1]), "=r"(r[2]), "=r"(r[3]) : "r"(addr));
}
__device__ __forceinline__ void mma_fp(float c[4], const uint32_t a[4],
                                       const uint32_t b[2]) {
    asm volatile(
        "mma.sync.aligned.m16n8k16.row.col.f32.f16.f16.f32 "
        "{%0,%1,%2,%3}, {%4,%5,%6,%7}, {%8,%9}, {%0,%1,%2,%3};"
        : "+f"(c[0]), "+f"(c[1]), "+f"(c[2]), "+f"(c[3])
        : "r"(a[0]), "r"(a[1]), "r"(a[2]), "r"(a[3]), "r"(b[0]), "r"(b[1]));
}
__device__ __forceinline__ uint32_t f2_to_h2u(float lo, float hi) {
    uint32_t r;
    asm("cvt.rn.f16x2.f32 %0, %1, %2;" : "=r"(r) : "f"(hi), "f"(lo));
    return r;
}
__device__ __forceinline__ float ex2f(float x) {
    float r; asm("ex2.approx.f32 %0, %1;" : "=f"(r) : "f"(x)); return r;
}
__device__ __forceinline__ uint32_t h2ex2(uint32_t a) {
    uint32_t r; asm("ex2.approx.f16x2 %0, %1;" : "=r"(r) : "r"(a)); return r;
}

// ========================= static device scratch ===========================
__device__ __half g_Qh[(size_t)Bv * Sv * Ev];
__device__ __half g_Kh[(size_t)Bv * Sv * Ev];
__device__ __half g_Vh[(size_t)Bv * Sv * Ev];
__device__ __half g_xf[(size_t)Bv * Sv * Ev];
__device__ __half g_of[(size_t)Bv * Sv * Ev];
__device__ __half g_wf[4][(size_t)Ev * Ev];

// ========================= fused fp32 -> fp16 convert ======================
__global__ void cvt_all_kernel(const float* __restrict__ x,
                               const float* __restrict__ w0,
                               const float* __restrict__ w1,
                               const float* __restrict__ w2,
                               const float* __restrict__ w3,
                               __half* __restrict__ xf, __half* __restrict__ wf)
{
    const int bid = blockIdx.x;
    const float* src;
    __half* dst;
    int i;
    if (bid < 8192) {
        src = x; dst = xf;
        i = bid * 256 + threadIdx.x;
    } else {
        const int wb = bid - 8192;
        const int wi = wb >> 10;
        const float* ws[4] = {w0, w1, w2, w3};
        src = ws[wi];
        dst = wf + (size_t)wi * Ev * Ev;
        i = (wb & 1023) * 256 + threadIdx.x;
    }
    float4 v = reinterpret_cast<const float4*>(src)[i];
    uint32_t* dp = reinterpret_cast<uint32_t*>(dst) + 2 * i;
    dp[0] = f2_to_h2u(v.x, v.y);
    dp[1] = f2_to_h2u(v.z, v.w);
}

// ========================= shared GEMM config (R12 best) ===================
// 128x128 CTA tile, 4 warps of 64x64, 128 threads, BK=32, 4-stage pipeline.
#define BK 32
#define ROWB 80
#define TILE_BYTES (128 * ROWB)
#define NCHW (Ev / BK)
#define STAGE_S (2 * TILE_BYTES)
#define NGSTG 4
#define GEMM_SMEM (NGSTG * STAGE_S)   // 81920
#define GTHREADS 128

__device__ __forceinline__ void load_stage_s(
    uint32_t sbase, int stage, int kc,
    const __half* A, const __half* B, int m0, int n0, int tid)
{
    const uint32_t st = sbase + stage * STAGE_S;
    const __half* srcs[2] = {A, B};
    const int row0[2] = {m0, n0};
#pragma unroll
    for (int t = 0; t < 2; ++t) {
#pragma unroll
        for (int p = 0; p < 4; ++p) {
            const int i = p * GTHREADS + tid;
            const int r = i >> 2;
            const int c = i & 3;
            const __half* g =
                srcs[t] + (size_t)(row0[t] + r) * Ev + kc * BK + c * 8;
            CP_ASYNC16(st + t * TILE_BYTES + r * ROWB + c * 16, g);
        }
    }
}

#define GEMM_MAINLOOP(A_, B_)                                              \
    load_stage_s(sb, 0, 0, A_, B_, m0, n0, tid); CP_COMMIT();              \
    load_stage_s(sb, 1, 1, A_, B_, m0, n0, tid); CP_COMMIT();              \
    load_stage_s(sb, 2, 2, A_, B_, m0, n0, tid); CP_COMMIT();              \
    CP_WAIT(2);                                                            \
    __syncthreads();                                                       \
    for (int c = 0; c < NCHW; ++c) {                                       \
        const int s = c & 3;                                               \
        if (c + 3 < NCHW) {                                                \
            load_stage_s(sb, (c + 3) & 3, c + 3, A_, B_, m0, n0, tid);     \
            CP_COMMIT();                                                   \
        } else { CP_COMMIT(); }                                            \
        const uint32_t stA = sb + s * STAGE_S;                             \
        const uint32_t stB = stA + TILE_BYTES;                             \
        _Pragma("unroll")                                                  \
        for (int ks = 0; ks < 2; ++ks) {                                   \
            const uint32_t kofs = ks * 32;                                 \
            uint32_t a[4][4], b[4][4];                                     \
            _Pragma("unroll")                                              \
            for (int p = 0; p < 4; ++p)                                    \
                ldsm4(stA + (uint32_t)(arow + p * 16) * ROWB + kofs + acol16, a[p]); \
            _Pragma("unroll")                                              \
            for (int p = 0; p < 4; ++p)                                    \
                ldsm4(stB + (uint32_t)(nrow + p * 16) * ROWB + kofs + bcol16, b[p]); \
            _Pragma("unroll")                                              \
            for (int mt = 0; mt < 4; ++mt)                                 \
                _Pragma("unroll")                                          \
                for (int nt = 0; nt < 8; ++nt)                             \
                    mma_fp(acc[mt][nt], a[mt], &b[nt >> 1][(nt & 1) * 2]); \
        }                                                                  \
        CP_WAIT(2);                                                        \
        __syncthreads();                                                   \
    }

// ========================= fused QKV GEMM (single-product fp16) ============
__global__ __launch_bounds__(GTHREADS, 2)
void gemm_qkv_kernel(const __half* __restrict__ A, const __half* __restrict__ W,
                     __half* __restrict__ Qo, __half* __restrict__ Ko,
                     __half* __restrict__ Vo)
{
    extern __shared__ __align__(128) char smem[];
    const uint32_t sb = smem_u32(smem);
    const int tid = threadIdx.x;
    const int wid = tid >> 5, lane = tid & 31;
    const int warp_m = wid & 1, warp_n = wid >> 1;
    const int m0 = blockIdx.y << 7;
    const int n0 = blockIdx.x << 7;
    const int z  = blockIdx.z;

    const __half* B = W + (size_t)z * Ev * Ev;
    __half* Out = (z == 0) ? Qo : ((z == 1) ? Ko : Vo);
    const float premul = (z == 0) ? (ATT_SCALE * LOG2E) : 1.0f;

    float acc[4][8][4];
#pragma unroll
    for (int mt = 0; mt < 4; ++mt)
#pragma unroll
        for (int nt = 0; nt < 8; ++nt)
#pragma unroll
            for (int q = 0; q < 4; ++q) acc[mt][nt][q] = 0.f;

    const int arow = warp_m * 64 + (lane & 15);
    const uint32_t acol16 = (uint32_t)((lane >> 4) << 4);
    const int nrow = warp_n * 64 + (((lane >> 4) & 1) << 3) + (lane & 7);
    const uint32_t bcol16 = (uint32_t)(((lane >> 3) & 1) << 4);

    GEMM_MAINLOOP(A, B)

    const int tr = lane >> 2;
    const int tc = (lane & 3) * 2;
    const int mb = m0 + warp_m * 64;
    const int nb = n0 + warp_n * 64;
#pragma unroll
    for (int mt = 0; mt < 4; ++mt) {
#pragma unroll
        for (int nt = 0; nt < 8; ++nt) {
            const int col = nb + nt * 8 + tc;
            const size_t r0 = (size_t)(mb + mt * 16 + tr) * Ev + col;
            const size_t r1 = (size_t)(mb + mt * 16 + tr + 8) * Ev + col;
            *reinterpret_cast<uint32_t*>(&Out[r0]) =
                f2_to_h2u(acc[mt][nt][0] * premul, acc[mt][nt][1] * premul);
            *reinterpret_cast<uint32_t*>(&Out[r1]) =
                f2_to_h2u(acc[mt][nt][2] * premul, acc[mt][nt][3] * premul);
        }
    }
}

// ========================= out-proj GEMM (single-product, fp32+bias) =======
__global__ __launch_bounds__(GTHREADS, 2)
void gemm_out_kernel(const __half* __restrict__ A, const __half* __restrict__ B,
                     const float* __restrict__ bias, float* __restrict__ C)
{
    extern __shared__ __align__(128) char smem[];
    const uint32_t sb = smem_u32(smem);
    const int tid = threadIdx.x;
    const int wid = tid >> 5, lane = tid & 31;
    const int warp_m = wid & 1, warp_n = wid >> 1;
    const int m0 = blockIdx.y << 7;
    const int n0 = blockIdx.x << 7;

    float acc[4][8][4];
#pragma unroll
    for (int mt = 0; mt < 4; ++mt)
#pragma unroll
        for (int nt = 0; nt < 8; ++nt)
#pragma unroll
            for (int q = 0; q < 4; ++q) acc[mt][nt][q] = 0.f;

    const int arow = warp_m * 64 + (lane & 15);
    const uint32_t acol16 = (uint32_t)((lane >> 4) << 4);
    const int nrow = warp_n * 64 + (((lane >> 4) & 1) << 3) + (lane & 7);
    const uint32_t bcol16 = (uint32_t)(((lane >> 3) & 1) << 4);

    GEMM_MAINLOOP(A, B)

    const int tr = lane >> 2;
    const int tc = (lane & 3) * 2;
    const int mb = m0 + warp_m * 64;
    const int nb = n0 + warp_n * 64;
#pragma unroll
    for (int mt = 0; mt < 4; ++mt) {
#pragma unroll
        for (int nt = 0; nt < 8; ++nt) {
            const int col = nb + nt * 8 + tc;
            const float b0 = bias[col], b1 = bias[col + 1];
            const size_t r0 = (size_t)(mb + mt * 16 + tr) * Ev + col;
            const size_t r1 = (size_t)(mb + mt * 16 + tr + 8) * Ev + col;
            float2 v0 = {acc[mt][nt][0] + b0, acc[mt][nt][1] + b1};
            float2 v1 = {acc[mt][nt][2] + b0, acc[mt][nt][3] + b1};
            *reinterpret_cast<float2*>(&C[r0]) = v0;
            *reinterpret_cast<float2*>(&C[r1]) = v1;
        }
    }
}

// ========================= tensor-core flash attention (R13 best) ==========
// 8 warps x 16 q-rows, fp16, log2-domain scores, ex2.f16x2 P, ones-column
// row-sum MMA, skip correction-scale when max unchanged (exact).
// Buggy l preserved. 3-stage mbarrier K/V pipeline. Output fp16.
#define NSTG 3
#define KVSTG (2 * 64 * 144)
#define ATT_SMEM (64 + 128 * 144 + NSTG * KVSTG)
#define H2_ONES 0x3C003C00u

__global__ __launch_bounds__(256, 2)
void attn_tc_kernel(const __half* __restrict__ Q, const __half* __restrict__ K,
                    const __half* __restrict__ V, __half* __restrict__ Of)
{
    extern __shared__ __align__(128) char smem[];
    const uint32_t sb = smem_u32(smem);
    const uint32_t sQ  = sb + 64;
    const uint32_t sKV = sQ + 128 * 144;

    const int tid = threadIdx.x;
    const int w = tid >> 5, lane = tid & 31;
    const int b  = blockIdx.x >> 4;
    const int h  = blockIdx.x & 15;
    const int q0 = blockIdx.y << 7;

    const __half* Qg = Q + ((size_t)b * Sv + q0) * Ev + h * HDv;
    const __half* Kg = K + (size_t)b * Sv * Ev + h * HDv;
    const __half* Vg = V + (size_t)b * Sv * Ev + h * HDv;

    if (tid == 0) {
#pragma unroll
        for (int s = 0; s < NSTG; ++s) {
            MBAR_INIT(sb + 8 * s, 256);
            MBAR_INIT(sb + 24 + 8 * s, 256);
        }
    }
    __syncthreads();

    for (int i = tid; i < 1024; i += 256) {
        const int r = i >> 3, c = i & 7;
        CP_ASYNC16(sQ + r * 144 + c * 16, Qg + (size_t)r * Ev + c * 8);
    }
    {
        const uint32_t st0 = sKV;
        for (int i = tid; i < 512; i += 256) {
            const int r = i >> 3, c = i & 7;
            CP_ASYNC16(st0 + r * 144 + c * 16, Kg + (size_t)r * Ev + c * 8);
            CP_ASYNC16(st0 + 64 * 144 + r * 144 + c * 16, Vg + (size_t)r * Ev + c * 8);
        }
        CPA_ARRIVE(sb + 0);
        const uint32_t st1 = sKV + KVSTG;
        const __half* Kp = Kg + (size_t)64 * Ev;
        const __half* Vp = Vg + (size_t)64 * Ev;
        for (int i = tid; i < 512; i += 256) {
            const int r = i >> 3, c = i & 7;
            CP_ASYNC16(st1 + r * 144 + c * 16, Kp + (size_t)r * Ev + c * 8);
            CP_ASYNC16(st1 + 64 * 144 + r * 144 + c * 16, Vp + (size_t)r * Ev + c * 8);
        }
        CPA_ARRIVE(sb + 8);
    }

    float acc[8][4];
#pragma unroll
    for (int j = 0; j < 8; ++j)
#pragma unroll
        for (int q = 0; q < 4; ++q) acc[j][q] = 0.f;
    float m0 = -CUDART_INF_F, m1 = -CUDART_INF_F;
    float l0 = 0.f, l1 = 0.f;

    uint32_t aQ[4][4];
    bool qLoaded = false;

    const uint32_t q_addr0 = sQ + (uint32_t)(16 * w + (lane & 15)) * 144
                                + ((lane >> 4) << 4);
    const int kq = lane & 7;
    const int kg16 = (lane >> 4) << 3;
    const int kg8  = ((lane >> 3) & 1) << 3;
    const uint32_t onesB[2] = {H2_ONES, H2_ONES};

    for (int kb = 0; kb < NKB; ++kb) {
        const int cur = kb % NSTG;
        MBAR_WAIT(sb + 8 * cur, (kb / NSTG) & 1);

        if (!qLoaded) {
#pragma unroll
            for (int s = 0; s < 4; ++s) ldsm4(q_addr0 + s * 32, aQ[s]);
            qLoaded = true;
        }

        const uint32_t sKst = sKV + (uint32_t)cur * KVSTG;
        const uint32_t sVst = sKst + 64 * 144;

        float sc[8][4];
#pragma unroll
        for (int j = 0; j < 8; ++j)
#pragma unroll
            for (int q = 0; q < 4; ++q) sc[j][q] = 0.f;

#pragma unroll
        for (int p = 0; p < 4; ++p) {
#pragma unroll
            for (int s = 0; s < 4; ++s) {
                uint32_t kf[4];
                ldsm4(sKst + (uint32_t)(16 * p + kg16 + kq) * 144
                           + (uint32_t)(16 * s + kg8) * 2, kf);
                mma_fp(sc[2 * p],     aQ[s], &kf[0]);
                mma_fp(sc[2 * p + 1], aQ[s], &kf[2]);
            }
        }

        if (kb + 2 < NKB) {
            const int kl = kb + 2;
            const int s2 = kl % NSTG;
            const int m = kl / NSTG;
            MBAR_WAIT(sb + 24 + 8 * s2, (m + 1) & 1);
            const uint32_t st = sKV + (uint32_t)s2 * KVSTG;
            const __half* Kp = Kg + (size_t)(kl * 64) * Ev;
            const __half* Vp = Vg + (size_t)(kl * 64) * Ev;
            for (int i = tid; i < 512; i += 256) {
                const int r = i >> 3, c = i & 7;
                CP_ASYNC16(st + r * 144 + c * 16, Kp + (size_t)r * Ev + c * 8);
                CP_ASYNC16(st + 64 * 144 + r * 144 + c * 16, Vp + (size_t)r * Ev + c * 8);
            }
            CPA_ARRIVE(sb + 8 * s2);
        }

        float mx0 = -CUDART_INF_F, mx1 = -CUDART_INF_F;
#pragma unroll
        for (int j = 0; j < 8; ++j) {
            mx0 = fmaxf(mx0, fmaxf(sc[j][0], sc[j][1]));
            mx1 = fmaxf(mx1, fmaxf(sc[j][2], sc[j][3]));
        }
        mx0 = fmaxf(mx0, __shfl_xor_sync(0xffffffffu, mx0, 1));
        mx0 = fmaxf(mx0, __shfl_xor_sync(0xffffffffu, mx0, 2));
        mx1 = fmaxf(mx1, __shfl_xor_sync(0xffffffffu, mx1, 1));
        mx1 = fmaxf(mx1, __shfl_xor_sync(0xffffffffu, mx1, 2));

        const float mn0 = fmaxf(m0, mx0);
        const float mn1 = fmaxf(m1, mx1);
        float co0 = 1.f, co1 = 1.f;
        const bool upd = (mn0 > m0) || (mn1 > m1);
        if (upd) {
            co0 = ex2f(m0 - mn0);
            co1 = ex2f(m1 - mn1);
#pragma unroll
            for (int j = 0; j < 8; ++j) {
                acc[j][0] *= co0; acc[j][1] *= co0;
                acc[j][2] *= co1; acc[j][3] *= co1;
            }
        }
        m0 = mn0; m1 = mn1;

        uint32_t ph01[8], ph23[8];
#pragma unroll
        for (int j = 0; j < 8; ++j) {
            ph01[j] = h2ex2(f2_to_h2u(sc[j][0] - mn0, sc[j][1] - mn0));
            ph23[j] = h2ex2(f2_to_h2u(sc[j][2] - mn1, sc[j][3] - mn1));
        }

        float sl[4] = {0.f, 0.f, 0.f, 0.f};
#pragma unroll
        for (int s = 0; s < 4; ++s) {
            const uint32_t aP[4] = {ph01[2 * s], ph23[2 * s],
                                    ph01[2 * s + 1], ph23[2 * s + 1]};
#pragma unroll
            for (int dp = 0; dp < 4; ++dp) {
                uint32_t vf[4];
                ldsm4t(sVst + (uint32_t)(16 * s + kg8 + kq) * 144
                            + (uint32_t)(16 * dp + kg16) * 2, vf);
                mma_fp(acc[2 * dp],     aP, &vf[0]);
                mma_fp(acc[2 * dp + 1], aP, &vf[2]);
            }
            mma_fp(sl, aP, onesB);
        }
        l0 = fmaf(sl[0], co0, sl[0]);
        l1 = fmaf(sl[2], co1, sl[2]);

        MBAR_ARRIVE(sb + 24 + 8 * cur);
    }

    const float inv0 = 1.f / l0;
    const float inv1 = 1.f / l1;
    const int row0 = q0 + 16 * w + (lane >> 2);
    const int colb = h * HDv + 2 * (lane & 3);
    __half* Ob = Of + (size_t)b * Sv * Ev;
#pragma unroll
    for (int j = 0; j < 8; ++j) {
        const int col = colb + 8 * j;
        const size_t i0 = (size_t)row0 * Ev + col;
        const size_t i1 = (size_t)(row0 + 8) * Ev + col;
        *reinterpret_cast<uint32_t*>(&Ob[i0]) =
            f2_to_h2u(acc[j][0] * inv0, acc[j][1] * inv0);
        *reinterpret_cast<uint32_t*>(&Ob[i1]) =
            f2_to_h2u(acc[j][2] * inv1, acc[j][3] * inv1);
    }
}

// ========================= launch ==========================================
extern "C" void kernel_launch(void* const* d_in, const int* in_sizes, int n_in,
                              void* d_out, int out_size)
{
    const float* x  = (const float*)d_in[0];
    const float* qw = (const float*)d_in[1];
    const float* kw = (const float*)d_in[2];
    const float* vw = (const float*)d_in[3];
    const float* ow = (const float*)d_in[4];
    const float* ob = (const float*)d_in[5];
    float* out = (float*)d_out;

    __half *Qh, *Kh, *Vh, *xf, *of, *wf;
    cudaGetSymbolAddress((void**)&Qh, g_Qh);
    cudaGetSymbolAddress((void**)&Kh, g_Kh);
    cudaGetSymbolAddress((void**)&Vh, g_Vh);
    cudaGetSymbolAddress((void**)&xf, g_xf);
    cudaGetSymbolAddress((void**)&of, g_of);
    cudaGetSymbolAddress((void**)&wf, g_wf);

    const int M = Bv * Sv;

    cvt_all_kernel<<<8192 + 4096, 256>>>(x, qw, kw, vw, ow, xf, wf);

    cudaFuncSetAttribute(gemm_qkv_kernel,
                         cudaFuncAttributeMaxDynamicSharedMemorySize, GEMM_SMEM);
    cudaFuncSetAttribute(gemm_out_kernel,
                         cudaFuncAttributeMaxDynamicSharedMemorySize, GEMM_SMEM);
    cudaFuncSetAttribute(attn_tc_kernel,
                         cudaFuncAttributeMaxDynamicSharedMemorySize, ATT_SMEM);

    gemm_qkv_kernel<<<dim3(Ev / 128, M / 128, 3), GTHREADS, GEMM_SMEM>>>(
        xf, wf, Qh, Kh, Vh);

    attn_tc_kernel<<<dim3(Bv * Hv, Sv / 128), 256, ATT_SMEM>>>(Qh, Kh, Vh, of);

    gemm_out_kernel<<<dim3(Ev / 128, M / 128), GTHREADS, GEMM_SMEM>>>(
        of, wf + 3 * (size_t)Ev * Ev, ob, out);
}

// round 16
// speedup vs baseline: 1.1145x; 1.0352x over previous
#include <cuda_runtime.h>
#include <cuda_fp16.h>
#include <math_constants.h>
#include <cstdint>

// Problem constants
#define Bv 4
#define Sv 2048
#define Ev 1024
#define Hv 16
#define HDv 64
#define NKB (Sv / 64)
#define ATT_SCALE 0.125f
#define LOG2E 1.4426950408889634f

// ========================= PTX helpers =====================================
__device__ __forceinline__ uint32_t smem_u32(const void* p) {
    uint32_t a;
    asm("{ .reg .u64 t; cvta.to.shared.u64 t, %1; cvt.u32.u64 %0, t; }"
        : "=r"(a) : "l"(p));
    return a;
}
#define CP_ASYNC16(sa, ga) \
    asm volatile("cp.async.cg.shared.global [%0], [%1], 16;" :: "r"(sa), "l"(ga))
#define CP_COMMIT()  asm volatile("cp.async.commit_group;" ::: "memory")
#define CP_WAIT(n)   asm volatile("cp.async.wait_group %0;" :: "n"(n) : "memory")

#define MBAR_INIT(addr, cnt) \
    asm volatile("mbarrier.init.shared.b64 [%0], %1;" :: "r"(addr), "r"((uint32_t)(cnt)) : "memory")
#define MBAR_ARRIVE(addr) \
    asm volatile("mbarrier.arrive.shared.b64 _, [%0];" :: "r"(addr) : "memory")
#define CPA_ARRIVE(addr) \
    asm volatile("cp.async.mbarrier.arrive.noinc.shared.b64 [%0];" :: "r"(addr) : "memory")
#define MBAR_WAIT(addr, ph) \
    asm volatile("{\n\t.reg .pred P;\n" \
                 "WL_%=:\n\t" \
                 "mbarrier.try_wait.parity.acquire.cta.shared::cta.b64 P, [%0], %1;\n\t" \
                 "@!P bra WL_%=;\n\t}" \
                 :: "r"(addr), "r"((uint32_t)(ph)) : "memory")

__device__ __forceinline__ void ldsm4(uint32_t addr, uint32_t r[4]) {
    asm volatile("ldmatrix.sync.aligned.m8n8.x4.shared.b16 {%0,%1,%2,%3}, [%4];"
                 : "=r"(r[0]), "=r"(r[1]), "=r"(r[2]), "=r"(r[3]) : "r"(addr));
}
__device__ __forceinline__ void ldsm4t(uint32_t addr, uint32_t r[4]) {
    asm volatile("ldmatrix.sync.aligned.m8n8.x4.trans.shared.b16 {%0,%1,%2,%3}, [%4];"
                 : "=r"(r[0]), "=r"(r[1]), "=r"(r[2]), "=r"(r[3]) : "r"(addr));
}
__device__ __forceinline__ void mma_fp(float c[4], const uint32_t a[4],
                                       const uint32_t b[2]) {
    asm volatile(
        "mma.sync.aligned.m16n8k16.row.col.f32.f16.f16.f32 "
        "{%0,%1,%2,%3}, {%4,%5,%6,%7}, {%8,%9}, {%0,%1,%2,%3};"
        : "+f"(c[0]), "+f"(c[1]), "+f"(c[2]), "+f"(c[3])
        : "r"(a[0]), "r"(a[1]), "r"(a[2]), "r"(a[3]), "r"(b[0]), "r"(b[1]));
}
__device__ __forceinline__ uint32_t f2_to_h2u(float lo, float hi) {
    uint32_t r;
    asm("cvt.rn.f16x2.f32 %0, %1, %2;" : "=r"(r) : "f"(hi), "f"(lo));
    return r;
}
__device__ __forceinline__ float ex2f(float x) {
    float r; asm("ex2.approx.f32 %0, %1;" : "=f"(r) : "f"(x)); return r;
}
__device__ __forceinline__ uint32_t h2ex2(uint32_t a) {
    uint32_t r; asm("ex2.approx.f16x2 %0, %1;" : "=r"(r) : "r"(a)); return r;
}

// ========================= static device scratch ===========================
__device__ __half g_Qh[(size_t)Bv * Sv * Ev];
__device__ __half g_Kh[(size_t)Bv * Sv * Ev];
__device__ __half g_Vh[(size_t)Bv * Sv * Ev];
__device__ __half g_xf[(size_t)Bv * Sv * Ev];
__device__ __half g_of[(size_t)Bv * Sv * Ev];
__device__ __half g_wf[4][(size_t)Ev * Ev];

// ========================= fused fp32 -> fp16 convert ======================
__global__ void cvt_all_kernel(const float* __restrict__ x,
                               const float* __restrict__ w0,
                               const float* __restrict__ w1,
                               const float* __restrict__ w2,
                               const float* __restrict__ w3,
                               __half* __restrict__ xf, __half* __restrict__ wf)
{
    const int bid = blockIdx.x;
    const float* src;
    __half* dst;
    int i;
    if (bid < 8192) {
        src = x; dst = xf;
        i = bid * 256 + threadIdx.x;
    } else {
        const int wb = bid - 8192;
        const int wi = wb >> 10;
        const float* ws[4] = {w0, w1, w2, w3};
        src = ws[wi];
        dst = wf + (size_t)wi * Ev * Ev;
        i = (wb & 1023) * 256 + threadIdx.x;
    }
    float4 v = reinterpret_cast<const float4*>(src)[i];
    uint32_t* dp = reinterpret_cast<uint32_t*>(dst) + 2 * i;
    dp[0] = f2_to_h2u(v.x, v.y);
    dp[1] = f2_to_h2u(v.z, v.w);
}

// ========================= shared GEMM config ==============================
// 128x128 CTA tile, 4 warps of 64x64, 128 threads, BK=32,
// 4-stage mbarrier-pipelined cp.async mainloop (no per-chunk syncthreads).
#define BK 32
#define ROWB 80
#define TILE_BYTES (128 * ROWB)
#define NCHW (Ev / BK)
#define STAGE_S (2 * TILE_BYTES)
#define NGSTG 4
#define GEMM_SMEM (64 + NGSTG * STAGE_S)   // 64 B barriers + 80 KB data
#define GTHREADS 128

__device__ __forceinline__ void load_stage_s(
    uint32_t sbase, int stage, int kc,
    const __half* A, const __half* B, int m0, int n0, int tid)
{
    const uint32_t st = sbase + 64 + stage * STAGE_S;
    const __half* srcs[2] = {A, B};
    const int row0[2] = {m0, n0};
#pragma unroll
    for (int t = 0; t < 2; ++t) {
#pragma unroll
        for (int p = 0; p < 4; ++p) {
            const int i = p * GTHREADS + tid;
            const int r = i >> 2;
            const int c = i & 3;
            const __half* g =
                srcs[t] + (size_t)(row0[t] + r) * Ev + kc * BK + c * 8;
            CP_ASYNC16(st + t * TILE_BYTES + r * ROWB + c * 16, g);
        }
    }
}

// full[s] = sb + 8*s ; empty[s] = sb + 32 + 8*s
#define GEMM_MAINLOOP(A_, B_)                                              \
    if (tid == 0) {                                                        \
        _Pragma("unroll")                                                  \
        for (int s = 0; s < NGSTG; ++s) {                                  \
            MBAR_INIT(sb + 8 * s, GTHREADS);                               \
            MBAR_INIT(sb + 32 + 8 * s, GTHREADS);                          \
        }                                                                  \
    }                                                                      \
    __syncthreads();                                                       \
    load_stage_s(sb, 0, 0, A_, B_, m0, n0, tid); CPA_ARRIVE(sb + 0);       \
    load_stage_s(sb, 1, 1, A_, B_, m0, n0, tid); CPA_ARRIVE(sb + 8);       \
    load_stage_s(sb, 2, 2, A_, B_, m0, n0, tid); CPA_ARRIVE(sb + 16);      \
    for (int c = 0; c < NCHW; ++c) {                                       \
        const int s = c & 3;                                               \
        MBAR_WAIT(sb + 8 * s, (c >> 2) & 1);                               \
        if (c + 3 < NCHW) {                                                \
            const int s3 = (c + 3) & 3;                                    \
            const int m3 = (c + 3) >> 2;                                   \
            MBAR_WAIT(sb + 32 + 8 * s3, (m3 + 1) & 1);                     \
            load_stage_s(sb, s3, c + 3, A_, B_, m0, n0, tid);              \
            CPA_ARRIVE(sb + 8 * s3);                                       \
        }                                                                  \
        const uint32_t stA = sb + 64 + s * STAGE_S;                        \
        const uint32_t stB = stA + TILE_BYTES;                             \
        _Pragma("unroll")                                                  \
        for (int ks = 0; ks < 2; ++ks) {                                   \
            const uint32_t kofs = ks * 32;                                 \
            uint32_t a[4][4], b[4][4];                                     \
            _Pragma("unroll")                                              \
            for (int p = 0; p < 4; ++p)                                    \
                ldsm4(stA + (uint32_t)(arow + p * 16) * ROWB + kofs + acol16, a[p]); \
            _Pragma("unroll")                                              \
            for (int p = 0; p < 4; ++p)                                    \
                ldsm4(stB + (uint32_t)(nrow + p * 16) * ROWB + kofs + bcol16, b[p]); \
            _Pragma("unroll")                                              \
            for (int mt = 0; mt < 4; ++mt)                                 \
                _Pragma("unroll")                                          \
                for (int nt = 0; nt < 8; ++nt)                             \
                    mma_fp(acc[mt][nt], a[mt], &b[nt >> 1][(nt & 1) * 2]); \
        }                                                                  \
        MBAR_ARRIVE(sb + 32 + 8 * s);                                      \
    }

// ========================= fused QKV GEMM (single-product fp16) ============
__global__ __launch_bounds__(GTHREADS, 2)
void gemm_qkv_kernel(const __half* __restrict__ A, const __half* __restrict__ W,
                     __half* __restrict__ Qo, __half* __restrict__ Ko,
                     __half* __restrict__ Vo)
{
    extern __shared__ __align__(128) char smem[];
    const uint32_t sb = smem_u32(smem);
    const int tid = threadIdx.x;
    const int wid = tid >> 5, lane = tid & 31;
    const int warp_m = wid & 1, warp_n = wid >> 1;
    const int m0 = blockIdx.y << 7;
    const int n0 = blockIdx.x << 7;
    const int z  = blockIdx.z;

    const __half* B = W + (size_t)z * Ev * Ev;
    __half* Out = (z == 0) ? Qo : ((z == 1) ? Ko : Vo);
    const float premul = (z == 0) ? (ATT_SCALE * LOG2E) : 1.0f;

    float acc[4][8][4];
#pragma unroll
    for (int mt = 0; mt < 4; ++mt)
#pragma unroll
        for (int nt = 0; nt < 8; ++nt)
#pragma unroll
            for (int q = 0; q < 4; ++q) acc[mt][nt][q] = 0.f;

    const int arow = warp_m * 64 + (lane & 15);
    const uint32_t acol16 = (uint32_t)((lane >> 4) << 4);
    const int nrow = warp_n * 64 + (((lane >> 4) & 1) << 3) + (lane & 7);
    const uint32_t bcol16 = (uint32_t)(((lane >> 3) & 1) << 4);

    GEMM_MAINLOOP(A, B)

    const int tr = lane >> 2;
    const int tc = (lane & 3) * 2;
    const int mb = m0 + warp_m * 64;
    const int nb = n0 + warp_n * 64;
#pragma unroll
    for (int mt = 0; mt < 4; ++mt) {
#pragma unroll
        for (int nt = 0; nt < 8; ++nt) {
            const int col = nb + nt * 8 + tc;
            const size_t r0 = (size_t)(mb + mt * 16 + tr) * Ev + col;
            const size_t r1 = (size_t)(mb + mt * 16 + tr + 8) * Ev + col;
            *reinterpret_cast<uint32_t*>(&Out[r0]) =
                f2_to_h2u(acc[mt][nt][0] * premul, acc[mt][nt][1] * premul);
            *reinterpret_cast<uint32_t*>(&Out[r1]) =
                f2_to_h2u(acc[mt][nt][2] * premul, acc[mt][nt][3] * premul);
        }
    }
}

// ========================= out-proj GEMM (single-product, fp32+bias) =======
__global__ __launch_bounds__(GTHREADS, 2)
void gemm_out_kernel(const __half* __restrict__ A, const __half* __restrict__ B,
                     const float* __restrict__ bias, float* __restrict__ C)
{
    extern __shared__ __align__(128) char smem[];
    const uint32_t sb = smem_u32(smem);
    const int tid = threadIdx.x;
    const int wid = tid >> 5, lane = tid & 31;
    const int warp_m = wid & 1, warp_n = wid >> 1;
    const int m0 = blockIdx.y << 7;
    const int n0 = blockIdx.x << 7;

    float acc[4][8][4];
#pragma unroll
    for (int mt = 0; mt < 4; ++mt)
#pragma unroll
        for (int nt = 0; nt < 8; ++nt)
#pragma unroll
            for (int q = 0; q < 4; ++q) acc[mt][nt][q] = 0.f;

    const int arow = warp_m * 64 + (lane & 15);
    const uint32_t acol16 = (uint32_t)((lane >> 4) << 4);
    const int nrow = warp_n * 64 + (((lane >> 4) & 1) << 3) + (lane & 7);
    const uint32_t bcol16 = (uint32_t)(((lane >> 3) & 1) << 4);

    GEMM_MAINLOOP(A, B)

    const int tr = lane >> 2;
    const int tc = (lane & 3) * 2;
    const int mb = m0 + warp_m * 64;
    const int nb = n0 + warp_n * 64;
#pragma unroll
    for (int mt = 0; mt < 4; ++mt) {
#pragma unroll
        for (int nt = 0; nt < 8; ++nt) {
            const int col = nb + nt * 8 + tc;
            const float b0 = bias[col], b1 = bias[col + 1];
            const size_t r0 = (size_t)(mb + mt * 16 + tr) * Ev + col;
            const size_t r1 = (size_t)(mb + mt * 16 + tr + 8) * Ev + col;
            float2 v0 = {acc[mt][nt][0] + b0, acc[mt][nt][1] + b1};
            float2 v1 = {acc[mt][nt][2] + b0, acc[mt][nt][3] + b1};
            *reinterpret_cast<float2*>(&C[r0]) = v0;
            *reinterpret_cast<float2*>(&C[r1]) = v1;
        }
    }
}

// ========================= tensor-core flash attention (R13 best) ==========
// 8 warps x 16 q-rows, fp16, log2-domain scores, ex2.f16x2 P, ones-column
// row-sum MMA, skip correction-scale when max unchanged (exact).
// Buggy l preserved. 3-stage mbarrier K/V pipeline. Output fp16.
#define NSTG 3
#define KVSTG (2 * 64 * 144)
#define ATT_SMEM (64 + 128 * 144 + NSTG * KVSTG)
#define H2_ONES 0x3C003C00u

__global__ __launch_bounds__(256, 2)
void attn_tc_kernel(const __half* __restrict__ Q, const __half* __restrict__ K,
                    const __half* __restrict__ V, __half* __restrict__ Of)
{
    extern __shared__ __align__(128) char smem[];
    const uint32_t sb = smem_u32(smem);
    const uint32_t sQ  = sb + 64;
    const uint32_t sKV = sQ + 128 * 144;

    const int tid = threadIdx.x;
    const int w = tid >> 5, lane = tid & 31;
    const int b  = blockIdx.x >> 4;
    const int h  = blockIdx.x & 15;
    const int q0 = blockIdx.y << 7;

    const __half* Qg = Q + ((size_t)b * Sv + q0) * Ev + h * HDv;
    const __half* Kg = K + (size_t)b * Sv * Ev + h * HDv;
    const __half* Vg = V + (size_t)b * Sv * Ev + h * HDv;

    if (tid == 0) {
#pragma unroll
        for (int s = 0; s < NSTG; ++s) {
            MBAR_INIT(sb + 8 * s, 256);
            MBAR_INIT(sb + 24 + 8 * s, 256);
        }
    }
    __syncthreads();

    for (int i = tid; i < 1024; i += 256) {
        const int r = i >> 3, c = i & 7;
        CP_ASYNC16(sQ + r * 144 + c * 16, Qg + (size_t)r * Ev + c * 8);
    }
    {
        const uint32_t st0 = sKV;
        for (int i = tid; i < 512; i += 256) {
            const int r = i >> 3, c = i & 7;
            CP_ASYNC16(st0 + r * 144 + c * 16, Kg + (size_t)r * Ev + c * 8);
            CP_ASYNC16(st0 + 64 * 144 + r * 144 + c * 16, Vg + (size_t)r * Ev + c * 8);
        }
        CPA_ARRIVE(sb + 0);
        const uint32_t st1 = sKV + KVSTG;
        const __half* Kp = Kg + (size_t)64 * Ev;
        const __half* Vp = Vg + (size_t)64 * Ev;
        for (int i = tid; i < 512; i += 256) {
            const int r = i >> 3, c = i & 7;
            CP_ASYNC16(st1 + r * 144 + c * 16, Kp + (size_t)r * Ev + c * 8);
            CP_ASYNC16(st1 + 64 * 144 + r * 144 + c * 16, Vp + (size_t)r * Ev + c * 8);
        }
        CPA_ARRIVE(sb + 8);
    }

    float acc[8][4];
#pragma unroll
    for (int j = 0; j < 8; ++j)
#pragma unroll
        for (int q = 0; q < 4; ++q) acc[j][q] = 0.f;
    float m0 = -CUDART_INF_F, m1 = -CUDART_INF_F;
    float l0 = 0.f, l1 = 0.f;

    uint32_t aQ[4][4];
    bool qLoaded = false;

    const uint32_t q_addr0 = sQ + (uint32_t)(16 * w + (lane & 15)) * 144
                                + ((lane >> 4) << 4);
    const int kq = lane & 7;
    const int kg16 = (lane >> 4) << 3;
    const int kg8  = ((lane >> 3) & 1) << 3;
    const uint32_t onesB[2] = {H2_ONES, H2_ONES};

    for (int kb = 0; kb < NKB; ++kb) {
        const int cur = kb % NSTG;
        MBAR_WAIT(sb + 8 * cur, (kb / NSTG) & 1);

        if (!qLoaded) {
#pragma unroll
            for (int s = 0; s < 4; ++s) ldsm4(q_addr0 + s * 32, aQ[s]);
            qLoaded = true;
        }

        const uint32_t sKst = sKV + (uint32_t)cur * KVSTG;
        const uint32_t sVst = sKst + 64 * 144;

        float sc[8][4];
#pragma unroll
        for (int j = 0; j < 8; ++j)
#pragma unroll
            for (int q = 0; q < 4; ++q) sc[j][q] = 0.f;

#pragma unroll
        for (int p = 0; p < 4; ++p) {
#pragma unroll
            for (int s = 0; s < 4; ++s) {
                uint32_t kf[4];
                ldsm4(sKst + (uint32_t)(16 * p + kg16 + kq) * 144
                           + (uint32_t)(16 * s + kg8) * 2, kf);
                mma_fp(sc[2 * p],     aQ[s], &kf[0]);
                mma_fp(sc[2 * p + 1], aQ[s], &kf[2]);
            }
        }

        if (kb + 2 < NKB) {
            const int kl = kb + 2;
            const int s2 = kl % NSTG;
            const int m = kl / NSTG;
            MBAR_WAIT(sb + 24 + 8 * s2, (m + 1) & 1);
            const uint32_t st = sKV + (uint32_t)s2 * KVSTG;
            const __half* Kp = Kg + (size_t)(kl * 64) * Ev;
            const __half* Vp = Vg + (size_t)(kl * 64) * Ev;
            for (int i = tid; i < 512; i += 256) {
                const int r = i >> 3, c = i & 7;
                CP_ASYNC16(st + r * 144 + c * 16, Kp + (size_t)r * Ev + c * 8);
                CP_ASYNC16(st + 64 * 144 + r * 144 + c * 16, Vp + (size_t)r * Ev + c * 8);
            }
            CPA_ARRIVE(sb + 8 * s2);
        }

        float mx0 = -CUDART_INF_F, mx1 = -CUDART_INF_F;
#pragma unroll
        for (int j = 0; j < 8; ++j) {
            mx0 = fmaxf(mx0, fmaxf(sc[j][0], sc[j][1]));
            mx1 = fmaxf(mx1, fmaxf(sc[j][2], sc[j][3]));
        }
        mx0 = fmaxf(mx0, __shfl_xor_sync(0xffffffffu, mx0, 1));
        mx0 = fmaxf(mx0, __shfl_xor_sync(0xffffffffu, mx0, 2));
        mx1 = fmaxf(mx1, __shfl_xor_sync(0xffffffffu, mx1, 1));
        mx1 = fmaxf(mx1, __shfl_xor_sync(0xffffffffu, mx1, 2));

        const float mn0 = fmaxf(m0, mx0);
        const float mn1 = fmaxf(m1, mx1);
        float co0 = 1.f, co1 = 1.f;
        const bool upd = (mn0 > m0) || (mn1 > m1);
        if (upd) {
            co0 = ex2f(m0 - mn0);
            co1 = ex2f(m1 - mn1);
#pragma unroll
            for (int j = 0; j < 8; ++j) {
                acc[j][0] *= co0; acc[j][1] *= co0;
                acc[j][2] *= co1; acc[j][3] *= co1;
            }
        }
        m0 = mn0; m1 = mn1;

        uint32_t ph01[8], ph23[8];
#pragma unroll
        for (int j = 0; j < 8; ++j) {
            ph01[j] = h2ex2(f2_to_h2u(sc[j][0] - mn0, sc[j][1] - mn0));
            ph23[j] = h2ex2(f2_to_h2u(sc[j][2] - mn1, sc[j][3] - mn1));
        }

        float sl[4] = {0.f, 0.f, 0.f, 0.f};
#pragma unroll
        for (int s = 0; s < 4; ++s) {
            const uint32_t aP[4] = {ph01[2 * s], ph23[2 * s],
                                    ph01[2 * s + 1], ph23[2 * s + 1]};
#pragma unroll
            for (int dp = 0; dp < 4; ++dp) {
                uint32_t vf[4];
                ldsm4t(sVst + (uint32_t)(16 * s + kg8 + kq) * 144
                            + (uint32_t)(16 * dp + kg16) * 2, vf);
                mma_fp(acc[2 * dp],     aP, &vf[0]);
                mma_fp(acc[2 * dp + 1], aP, &vf[2]);
            }
            mma_fp(sl, aP, onesB);
        }
        l0 = fmaf(sl[0], co0, sl[0]);
        l1 = fmaf(sl[2], co1, sl[2]);

        MBAR_ARRIVE(sb + 24 + 8 * cur);
    }

    const float inv0 = 1.f / l0;
    const float inv1 = 1.f / l1;
    const int row0 = q0 + 16 * w + (lane >> 2);
    const int colb = h * HDv + 2 * (lane & 3);
    __half* Ob = Of + (size_t)b * Sv * Ev;
#pragma unroll
    for (int j = 0; j < 8; ++j) {
        const int col = colb + 8 * j;
        const size_t i0 = (size_t)row0 * Ev + col;
        const size_t i1 = (size_t)(row0 + 8) * Ev + col;
        *reinterpret_cast<uint32_t*>(&Ob[i0]) =
            f2_to_h2u(acc[j][0] * inv0, acc[j][1] * inv0);
        *reinterpret_cast<uint32_t*>(&Ob[i1]) =
            f2_to_h2u(acc[j][2] * inv1, acc[j][3] * inv1);
    }
}

// ========================= launch ==========================================
extern "C" void kernel_launch(void* const* d_in, const int* in_sizes, int n_in,
                              void* d_out, int out_size)
{
    const float* x  = (const float*)d_in[0];
    const float* qw = (const float*)d_in[1];
    const float* kw = (const float*)d_in[2];
    const float* vw = (const float*)d_in[3];
    const float* ow = (const float*)d_in[4];
    const float* ob = (const float*)d_in[5];
    float* out = (float*)d_out;

    __half *Qh, *Kh, *Vh, *xf, *of, *wf;
    cudaGetSymbolAddress((void**)&Qh, g_Qh);
    cudaGetSymbolAddress((void**)&Kh, g_Kh);
    cudaGetSymbolAddress((void**)&Vh, g_Vh);
    cudaGetSymbolAddress((void**)&xf, g_xf);
    cudaGetSymbolAddress((void**)&of, g_of);
    cudaGetSymbolAddress((void**)&wf, g_wf);

    const int M = Bv * Sv;

    cvt_all_kernel<<<8192 + 4096, 256>>>(x, qw, kw, vw, ow, xf, wf);

    cudaFuncSetAttribute(gemm_qkv_kernel,
                         cudaFuncAttributeMaxDynamicSharedMemorySize, GEMM_SMEM);
    cudaFuncSetAttribute(gemm_out_kernel,
                         cudaFuncAttributeMaxDynamicSharedMemorySize, GEMM_SMEM);
    cudaFuncSetAttribute(attn_tc_kernel,
                         cudaFuncAttributeMaxDynamicSharedMemorySize, ATT_SMEM);

    gemm_qkv_kernel<<<dim3(Ev / 128, M / 128, 3), GTHREADS, GEMM_SMEM>>>(
        xf, wf, Qh, Kh, Vh);

    attn_tc_kernel<<<dim3(Bv * Hv, Sv / 128), 256, ATT_SMEM>>>(Qh, Kh, Vh, of);

    gemm_out_kernel<<<dim3(Ev / 128, M / 128), GTHREADS, GEMM_SMEM>>>(
        of, wf + 3 * (size_t)Ev * Ev, ob, out);
}